// round 1
// baseline (speedup 1.0000x reference)
#include <cuda_runtime.h>
#include <math.h>

#define Bn 8
#define Cc 96
#define C2 192
#define Npix 3136
#define KK 9
#define BNtot 25088   // Bn*Npix

// ---------------- scratch ----------------
__device__ float g_h  [Bn*Cc*Npix];     // raw gemm outputs (fc1, later fc2) (B,C,N)
__device__ float g_ht [Bn*Npix*Cc];     // BN'd h, transposed (B,N,C)
__device__ float g_xnt[Bn*Npix*Cc];     // L2-normalized h, transposed (B,N,C)
__device__ float g_sq [Bn*Npix];        // ||xn||^2 per column
__device__ int   g_idx[Bn*Npix*KK];     // knn indices
__device__ float g_y  [Bn*C2*Npix];     // interleaved features / g2 output (B,2C,N)
__device__ float g_t1 [Bn*C2*Npix];     // g1 output (B,2C,N)
__device__ float g_ps [C2*Bn];
__device__ float g_pss[C2*Bn];
__device__ float g_scale[C2];
__device__ float g_shift[C2];

// ---------------- generic SGEMM: Out[b,m,n] = sum_k W[m,k]*Act[b,k,n] + bias[m] ----------------
#define SG_BM 64
#define SG_BN 64
#define SG_BK 16

__global__ __launch_bounds__(256) void sgemm_bias_kernel(
    const float* __restrict__ W, const float* __restrict__ Act,
    const float* __restrict__ bias, float* __restrict__ Out,
    int M, int Kd)
{
    int b  = blockIdx.z;
    const float* Bm = Act + (size_t)b * Kd * Npix;
    float* C = Out + (size_t)b * M * Npix;
    int n0 = blockIdx.x * SG_BN;
    int m0 = blockIdx.y * SG_BM;

    __shared__ float As[SG_BK][SG_BM + 4];   // [k][m], padded
    __shared__ float Bs[SG_BK][SG_BN];       // [k][n]

    int tid = threadIdx.x;
    int tx = tid & 15, ty = tid >> 4;
    float acc[4][4];
    #pragma unroll
    for (int i = 0; i < 4; i++)
        #pragma unroll
        for (int j = 0; j < 4; j++) acc[i][j] = 0.f;

    for (int k0 = 0; k0 < Kd; k0 += SG_BK) {
        // A tile: BM x BK (transpose into [k][m])
        for (int e = tid; e < SG_BM * SG_BK; e += 256) {
            int mi = e >> 4;
            int kj = e & 15;
            int gm = m0 + mi;
            As[kj][mi] = (gm < M) ? W[(size_t)gm * Kd + k0 + kj] : 0.f;
        }
        // B tile: BK x BN
        for (int e = tid; e < SG_BK * SG_BN; e += 256) {
            int ki = e >> 6;
            int nj = e & 63;
            Bs[ki][nj] = Bm[(size_t)(k0 + ki) * Npix + n0 + nj];
        }
        __syncthreads();
        #pragma unroll
        for (int k = 0; k < SG_BK; k++) {
            float4 a4 = *(const float4*)&As[k][ty * 4];
            float4 b4 = *(const float4*)&Bs[k][tx * 4];
            float av[4] = {a4.x, a4.y, a4.z, a4.w};
            float bv[4] = {b4.x, b4.y, b4.z, b4.w};
            #pragma unroll
            for (int i = 0; i < 4; i++)
                #pragma unroll
                for (int j = 0; j < 4; j++) acc[i][j] += av[i] * bv[j];
        }
        __syncthreads();
    }
    #pragma unroll
    for (int i = 0; i < 4; i++) {
        int gm = m0 + ty * 4 + i;
        if (gm < M) {
            float bv = bias[gm];
            float4 o;
            o.x = acc[i][0] + bv; o.y = acc[i][1] + bv;
            o.z = acc[i][2] + bv; o.w = acc[i][3] + bv;
            *(float4*)&C[(size_t)gm * Npix + n0 + tx * 4] = o;
        }
    }
}

// ---------------- BN stats (deterministic two-stage) ----------------
__global__ __launch_bounds__(256) void bn_partial_kernel(
    const float* __restrict__ X, float* __restrict__ ps, float* __restrict__ pss, int C)
{
    int c = blockIdx.x, b = blockIdx.y;
    const float* p = X + ((size_t)b * C + c) * Npix;
    float s = 0.f, ss = 0.f;
    for (int n = threadIdx.x; n < Npix; n += 256) {
        float v = p[n]; s += v; ss += v * v;
    }
    __shared__ float sh0[256], sh1[256];
    int tid = threadIdx.x;
    sh0[tid] = s; sh1[tid] = ss;
    __syncthreads();
    for (int o = 128; o > 0; o >>= 1) {
        if (tid < o) { sh0[tid] += sh0[tid + o]; sh1[tid] += sh1[tid + o]; }
        __syncthreads();
    }
    if (tid == 0) { ps[c * Bn + b] = sh0[0]; pss[c * Bn + b] = sh1[0]; }
}

__global__ void bn_finalize_kernel(
    const float* __restrict__ ps, const float* __restrict__ pss,
    const float* __restrict__ g, const float* __restrict__ be,
    float* __restrict__ scale, float* __restrict__ shift, int C)
{
    int c = blockIdx.x * blockDim.x + threadIdx.x;
    if (c >= C) return;
    float s = 0.f, ss = 0.f;
    for (int b = 0; b < Bn; b++) { s += ps[c * Bn + b]; ss += pss[c * Bn + b]; }
    float mean = s * (1.0f / (float)BNtot);
    float var  = ss * (1.0f / (float)BNtot) - mean * mean;
    float inv  = rsqrtf(var + 1e-5f);
    float sc = g[c] * inv;
    scale[c] = sc;
    shift[c] = be[c] - mean * sc;
}

// ---------------- BN apply + transpose + L2 normalize (after fc1) ----------------
__global__ __launch_bounds__(256) void bn_norm_kernel(
    const float* __restrict__ Hraw, const float* __restrict__ scale, const float* __restrict__ shift,
    float* __restrict__ Ht, float* __restrict__ Xnt, float* __restrict__ Sq)
{
    int n = blockIdx.x * 256 + threadIdx.x;
    int b = blockIdx.y;
    if (n >= Npix) return;
    size_t obase = ((size_t)b * Npix + n) * Cc;
    float ss = 0.f;
    #pragma unroll 4
    for (int c = 0; c < Cc; c++) {
        float v = Hraw[((size_t)b * Cc + c) * Npix + n] * scale[c] + shift[c];
        Ht[obase + c] = v;
        ss += v * v;
    }
    float nrm = sqrtf(ss);
    float rn = 1.0f / fmaxf(nrm, 1e-12f);
    Sq[(size_t)b * Npix + n] = ss * rn * rn;
    #pragma unroll 4
    for (int c = 0; c < Cc; c++) Xnt[obase + c] = Ht[obase + c] * rn;
}

// ---------------- fused similarity GEMM + top-9 ----------------
#define KTR 64
#define KTC 64
#define KPAD 68
#define KNN_SMEM_FLOATS (Cc*KPAD*2 + KTR*65 + KTC)
#define KNN_SMEM_BYTES  (KNN_SMEM_FLOATS*4)

__global__ __launch_bounds__(256) void knn_kernel(
    const float* __restrict__ Xnt, const float* __restrict__ Sq, int* __restrict__ Idx)
{
    extern __shared__ float smem[];
    float* Asm = smem;                     // [c][r] stride KPAD
    float* Bsm = Asm + Cc * KPAD;          // [c][j] stride KPAD
    float* Sc  = Bsm + Cc * KPAD;          // [r][j] stride 65
    float* SqS = Sc + KTR * 65;            // [j]

    int tid = threadIdx.x;
    int b = blockIdx.y;
    int row0 = blockIdx.x * KTR;
    const float* X = Xnt + (size_t)b * Npix * Cc;

    // load query rows (transposed)
    for (int e = tid; e < KTR * Cc; e += 256) {
        int r = e / Cc, c = e - r * Cc;
        Asm[c * KPAD + r] = X[(size_t)row0 * Cc + e];
    }

    float tv[KK]; int ti[KK];
    #pragma unroll
    for (int q = 0; q < KK; q++) { tv[q] = -1e30f; ti[q] = 0; }

    int tx = tid & 15, ty = tid >> 4;
    int pr = tid >> 2, pch = tid & 3;

    for (int t = 0; t < Npix / KTC; t++) {
        int m0 = t * KTC;
        __syncthreads();
        for (int e = tid; e < KTC * Cc; e += 256) {
            int r = e / Cc, c = e - r * Cc;
            Bsm[c * KPAD + r] = X[(size_t)m0 * Cc + e];
        }
        if (tid < KTC) SqS[tid] = Sq[(size_t)b * Npix + m0 + tid];
        __syncthreads();

        // phase 1: 64x64 score tile, 4x4 microtile per thread
        float acc[4][4];
        #pragma unroll
        for (int i = 0; i < 4; i++)
            #pragma unroll
            for (int j = 0; j < 4; j++) acc[i][j] = 0.f;
        #pragma unroll 4
        for (int c = 0; c < Cc; c++) {
            float4 a4 = *(const float4*)&Asm[c * KPAD + ty * 4];
            float4 b4 = *(const float4*)&Bsm[c * KPAD + tx * 4];
            float av[4] = {a4.x, a4.y, a4.z, a4.w};
            float bv[4] = {b4.x, b4.y, b4.z, b4.w};
            #pragma unroll
            for (int i = 0; i < 4; i++)
                #pragma unroll
                for (int j = 0; j < 4; j++) acc[i][j] += av[i] * bv[j];
        }
        #pragma unroll
        for (int i = 0; i < 4; i++)
            #pragma unroll
            for (int j = 0; j < 4; j++)
                Sc[(ty * 4 + i) * 65 + tx * 4 + j] = 2.0f * acc[i][j] - SqS[tx * 4 + j];
        __syncthreads();

        // phase 2: each of 4 threads per row scans 16 scores, keeps sorted top-9
        const float* srow = &Sc[pr * 65 + pch * 16];
        #pragma unroll
        for (int j = 0; j < 16; j++) {
            float s = srow[j];
            if (s > tv[KK - 1]) {
                int m = m0 + pch * 16 + j;
                tv[KK - 1] = s; ti[KK - 1] = m;
                #pragma unroll
                for (int p = KK - 1; p > 0; p--) {
                    if (tv[p] > tv[p - 1]) {
                        float fv = tv[p]; tv[p] = tv[p - 1]; tv[p - 1] = fv;
                        int iv = ti[p]; ti[p] = ti[p - 1]; ti[p - 1] = iv;
                    }
                }
            }
        }
    }
    __syncthreads();

    // merge 4 partial top-9 lists per row (reuse Asm region)
    float* cv = Asm;                      // [r][36]
    int*   ci = (int*)(Asm + KTR * 36);   // [r][36]
    #pragma unroll
    for (int q = 0; q < KK; q++) {
        cv[pr * 36 + pch * KK + q] = tv[q];
        ci[pr * 36 + pch * KK + q] = ti[q];
    }
    __syncthreads();
    if (tid < KTR) {
        float* crow = &cv[tid * 36];
        int*   irow = &ci[tid * 36];
        int*   orow = &Idx[((size_t)b * Npix + row0 + tid) * KK];
        for (int q = 0; q < KK; q++) {
            float best = -1e38f; int bj = 0;
            for (int j = 0; j < 36; j++)
                if (crow[j] > best) { best = crow[j]; bj = j; }
            orow[q] = irow[bj];
            crow[bj] = -1e38f;
        }
    }
}

// ---------------- gather + max-relative + interleave ----------------
__global__ __launch_bounds__(256) void build_y_kernel(
    const float* __restrict__ Ht, const int* __restrict__ Idx, float* __restrict__ Y)
{
    int warp = threadIdx.x >> 5, lane = threadIdx.x & 31;
    int n = blockIdx.x * 8 + warp;
    int b = blockIdx.y;
    const float* hb = Ht + (size_t)b * Npix * Cc;
    const int* irow = &Idx[((size_t)b * Npix + n) * KK];
    int idx[KK];
    #pragma unroll
    for (int k = 0; k < KK; k++) idx[k] = irow[k];
    float* yb = Y + (size_t)b * C2 * Npix;
    #pragma unroll
    for (int cc = 0; cc < 3; cc++) {
        int c = lane + cc * 32;
        float v = hb[(size_t)n * Cc + c];
        float mx = -1e30f;
        #pragma unroll
        for (int k = 0; k < KK; k++) mx = fmaxf(mx, hb[(size_t)idx[k] * Cc + c]);
        yb[(size_t)(2 * c) * Npix + n]     = v;
        yb[(size_t)(2 * c + 1) * Npix + n] = mx - v;
    }
}

// ---------------- BN apply (+ exact GELU) in place ----------------
__global__ __launch_bounds__(256) void bn_act_kernel(
    float* __restrict__ X, const float* __restrict__ scale, const float* __restrict__ shift, int C)
{
    size_t i = (size_t)blockIdx.x * 256 + threadIdx.x;
    int c = (int)((i / Npix) % C);
    float v = X[i] * scale[c] + shift[c];
    v = 0.5f * v * (1.0f + erff(v * 0.70710678118654752f));
    X[i] = v;
}

// ---------------- final BN + residual ----------------
__global__ __launch_bounds__(256) void bn_res_out_kernel(
    const float* __restrict__ raw, const float* __restrict__ scale, const float* __restrict__ shift,
    const float* __restrict__ x, float* __restrict__ out)
{
    size_t i = (size_t)blockIdx.x * 256 + threadIdx.x;
    int c = (int)((i / Npix) % Cc);
    out[i] = raw[i] * scale[c] + shift[c] + x[i];
}

// ---------------- launch ----------------
extern "C" void kernel_launch(void* const* d_in, const int* in_sizes, int n_in,
                              void* d_out, int out_size)
{
    const float* x      = (const float*)d_in[0];
    const float* fc1_w  = (const float*)d_in[1];
    const float* fc1_b  = (const float*)d_in[2];
    const float* fc1_g  = (const float*)d_in[3];
    const float* fc1_be = (const float*)d_in[4];
    const float* g1_w   = (const float*)d_in[5];
    const float* g1_b   = (const float*)d_in[6];
    const float* g1_g   = (const float*)d_in[7];
    const float* g1_be  = (const float*)d_in[8];
    const float* g2_w   = (const float*)d_in[9];
    const float* g2_b   = (const float*)d_in[10];
    const float* g2_g   = (const float*)d_in[11];
    const float* g2_be  = (const float*)d_in[12];
    const float* fc2_w  = (const float*)d_in[13];
    const float* fc2_b  = (const float*)d_in[14];
    const float* fc2_g  = (const float*)d_in[15];
    const float* fc2_be = (const float*)d_in[16];

    float *h, *ht, *xnt, *sq, *y, *t1, *ps, *pss, *scale, *shift;
    int* idx;
    cudaGetSymbolAddress((void**)&h,     g_h);
    cudaGetSymbolAddress((void**)&ht,    g_ht);
    cudaGetSymbolAddress((void**)&xnt,   g_xnt);
    cudaGetSymbolAddress((void**)&sq,    g_sq);
    cudaGetSymbolAddress((void**)&idx,   g_idx);
    cudaGetSymbolAddress((void**)&y,     g_y);
    cudaGetSymbolAddress((void**)&t1,    g_t1);
    cudaGetSymbolAddress((void**)&ps,    g_ps);
    cudaGetSymbolAddress((void**)&pss,   g_pss);
    cudaGetSymbolAddress((void**)&scale, g_scale);
    cudaGetSymbolAddress((void**)&shift, g_shift);

    cudaFuncSetAttribute(knn_kernel, cudaFuncAttributeMaxDynamicSharedMemorySize, KNN_SMEM_BYTES);

    // fc1: h_raw = fc1_w @ x + b
    sgemm_bias_kernel<<<dim3(Npix / SG_BN, 2, Bn), 256>>>(fc1_w, x, fc1_b, h, Cc, Cc);
    bn_partial_kernel<<<dim3(Cc, Bn), 256>>>(h, ps, pss, Cc);
    bn_finalize_kernel<<<1, 256>>>(ps, pss, fc1_g, fc1_be, scale, shift, Cc);
    bn_norm_kernel<<<dim3((Npix + 255) / 256, Bn), 256>>>(h, scale, shift, ht, xnt, sq);

    // knn
    knn_kernel<<<dim3(Npix / KTR, Bn), 256, KNN_SMEM_BYTES>>>(xnt, sq, idx);

    // gather + interleave
    build_y_kernel<<<dim3(Npix / 8, Bn), 256>>>(ht, idx, y);

    // g1
    sgemm_bias_kernel<<<dim3(Npix / SG_BN, 3, Bn), 256>>>(g1_w, y, g1_b, t1, C2, C2);
    bn_partial_kernel<<<dim3(C2, Bn), 256>>>(t1, ps, pss, C2);
    bn_finalize_kernel<<<1, 256>>>(ps, pss, g1_g, g1_be, scale, shift, C2);
    bn_act_kernel<<<(Bn * C2 * Npix) / 256, 256>>>(t1, scale, shift, C2);

    // g2
    sgemm_bias_kernel<<<dim3(Npix / SG_BN, 3, Bn), 256>>>(g2_w, t1, g2_b, y, C2, C2);
    bn_partial_kernel<<<dim3(C2, Bn), 256>>>(y, ps, pss, C2);
    bn_finalize_kernel<<<1, 256>>>(ps, pss, g2_g, g2_be, scale, shift, C2);
    bn_act_kernel<<<(Bn * C2 * Npix) / 256, 256>>>(y, scale, shift, C2);

    // fc2
    sgemm_bias_kernel<<<dim3(Npix / SG_BN, 2, Bn), 256>>>(fc2_w, y, fc2_b, h, Cc, C2);
    bn_partial_kernel<<<dim3(Cc, Bn), 256>>>(h, ps, pss, Cc);
    bn_finalize_kernel<<<1, 256>>>(ps, pss, fc2_g, fc2_be, scale, shift, Cc);
    bn_res_out_kernel<<<(Bn * Cc * Npix) / 256, 256>>>(h, scale, shift, x, (float*)d_out);
}